// round 5
// baseline (speedup 1.0000x reference)
#include <cuda_runtime.h>
#include <cuda_bf16.h>

#define NN 4096
#define MM 512
#define DD 32
#define TMAX 16
#define NBLK 128        // rowstats blocks, 32 rows each

typedef unsigned long long ull;

// Per-row stats + per-block err partials (fully rewritten every launch -> no zeroing needed)
__device__ float g_R[NN], g_S[NN], g_T[NN];
__device__ float g_Epart[NBLK][TMAX];

// sm_103a packed fp32 FMA (FFMA2). Element 0 = low 32 bits.
__device__ __forceinline__ ull ffma2(ull a, ull b, ull c) {
    ull d;
    asm("fma.rn.f32x2 %0, %1, %2, %3;" : "=l"(d) : "l"(a), "l"(b), "l"(c));
    return d;
}
__device__ __forceinline__ ull fdup(float v) {
    unsigned u = __float_as_uint(v);
    return ((ull)u << 32) | (ull)u;
}
__device__ __forceinline__ float flo(ull v) { return __uint_as_float((unsigned)v); }
__device__ __forceinline__ float fhi(ull v) { return __uint_as_float((unsigned)(v >> 32)); }

// Dynamic smem layout: yT[32][512] (64KB) | yn2[512] | part[3][8][32]
#define SMEM_BYTES ((32 * 512 + 512 + 3 * 8 * 32) * 4)

// ---------------------------------------------------------------------------
// Kernel 1: row statistics, GEMM-style.
// lanes = n (one row per lane, 32 rows per block), x duplicated-packed in regs,
// y transposed in smem and read as broadcast LDS.128, m-tiled by 8 with 4
// packed f32x2 accumulators. d2 = |x|^2 + |y|^2 - 2 x.y.
// Tail: warp 0 combines warp partials (fixed order -> deterministic) and
// computes per-block err contributions for iterations 1..TMAX.
// ---------------------------------------------------------------------------
__global__ __launch_bounds__(256) void rowstats_kernel(
    const float* __restrict__ x,   // [NN, DD]
    const float* __restrict__ y,   // [MM, DD]
    const float* __restrict__ r)   // [NN, MM]
{
    extern __shared__ float smem_dyn[];
    float* yT   = smem_dyn;              // [d][m] : 32 x 512
    float* yn2  = smem_dyn + 32 * 512;   // [512]
    float* part = yn2 + 512;             // [3][8][32]

    const int tid  = threadIdx.x;
    const int warp = tid >> 5;
    const int lane = tid & 31;
    const int nb   = blockIdx.x << 5;
    const int n    = nb + lane;

    // ---- stage y transposed + |y|^2 (thread t handles m = t and m = t+256;
    //      STS bank = m%32 = lane -> conflict-free)
    {
        const float4* ya = (const float4*)(y + tid * DD);
        const float4* yb = (const float4*)(y + (tid + 256) * DD);
        float sa = 0.f, sb = 0.f;
#pragma unroll
        for (int k = 0; k < 8; k++) {
            float4 a = ya[k], b = yb[k];
            yT[(4 * k + 0) * 512 + tid] = a.x;
            yT[(4 * k + 1) * 512 + tid] = a.y;
            yT[(4 * k + 2) * 512 + tid] = a.z;
            yT[(4 * k + 3) * 512 + tid] = a.w;
            yT[(4 * k + 0) * 512 + tid + 256] = b.x;
            yT[(4 * k + 1) * 512 + tid + 256] = b.y;
            yT[(4 * k + 2) * 512 + tid + 256] = b.z;
            yT[(4 * k + 3) * 512 + tid + 256] = b.w;
            sa = fmaf(a.x, a.x, sa); sa = fmaf(a.y, a.y, sa);
            sa = fmaf(a.z, a.z, sa); sa = fmaf(a.w, a.w, sa);
            sb = fmaf(b.x, b.x, sb); sb = fmaf(b.y, b.y, sb);
            sb = fmaf(b.z, b.z, sb); sb = fmaf(b.w, b.w, sb);
        }
        yn2[tid] = sa;
        yn2[tid + 256] = sb;
    }

    // ---- this lane's x row: duplicated-packed into 32 x f32x2 regs + |x|^2
    ull   xd[DD];
    float xn2 = 0.f;
    {
        const float4* xv = (const float4*)(x + n * DD);
#pragma unroll
        for (int k = 0; k < 8; k++) {
            float4 a = xv[k];
            xd[4 * k + 0] = fdup(a.x); xd[4 * k + 1] = fdup(a.y);
            xd[4 * k + 2] = fdup(a.z); xd[4 * k + 3] = fdup(a.w);
            xn2 = fmaf(a.x, a.x, xn2); xn2 = fmaf(a.y, a.y, xn2);
            xn2 = fmaf(a.z, a.z, xn2); xn2 = fmaf(a.w, a.w, xn2);
        }
    }
    __syncthreads();

    float Racc = 0.f, Sacc = 0.f, Tacc = 0.f;
    const int    mc   = warp << 6;                 // this warp's 64-column chunk
    const float* rrow = r + (size_t)n * MM;

#pragma unroll
    for (int mt = 0; mt < 8; mt++) {
        const int mb = mc + (mt << 3);             // m-tile of 8
        ull A0 = 0, A1 = 0, A2 = 0, A3 = 0;        // 8 packed dot accumulators
#pragma unroll
        for (int d = 0; d < DD; d++) {
            const ulonglong2* yp = (const ulonglong2*)(yT + d * 512 + mb);
            ulonglong2 p = yp[0];                  // broadcast LDS.128: m..m+3
            ulonglong2 q = yp[1];                  // broadcast LDS.128: m+4..m+7
            A0 = ffma2(xd[d], p.x, A0);
            A1 = ffma2(xd[d], p.y, A1);
            A2 = ffma2(xd[d], q.x, A2);
            A3 = ffma2(xd[d], q.y, A3);
        }
        float dot[8] = { flo(A0), fhi(A0), flo(A1), fhi(A1),
                         flo(A2), fhi(A2), flo(A3), fhi(A3) };
        float4 r4a = ((const float4*)(rrow + mb))[0];
        float4 r4b = ((const float4*)(rrow + mb))[1];
        float rv[8] = { r4a.x, r4a.y, r4a.z, r4a.w, r4b.x, r4b.y, r4b.z, r4b.w };
        float4 y2a = ((const float4*)(yn2 + mb))[0];
        float4 y2b = ((const float4*)(yn2 + mb))[1];
        float yy[8] = { y2a.x, y2a.y, y2a.z, y2a.w, y2b.x, y2b.y, y2b.z, y2b.w };
#pragma unroll
        for (int j = 0; j < 8; j++) {
            float d2 = fmaf(-2.f, dot[j], xn2 + yy[j]);
            d2 = fmaxf(d2, 0.f);
            float C = sqrtf(d2);
            float K = __expf(-0.5f * C);           // exp(-C/EPS), EPS=2
            Racc += K;
            float Kr = K * rv[j];
            Sacc += Kr;
            Tacc = fmaf(Kr, C, Tacc);
        }
    }

    // ---- combine warp partials in fixed order (deterministic), write stats
    part[(0 * 8 + warp) * 32 + lane] = Racc;
    part[(1 * 8 + warp) * 32 + lane] = Sacc;
    part[(2 * 8 + warp) * 32 + lane] = Tacc;
    __syncthreads();

    if (warp == 0) {
        float R = 0.f, S = 0.f, T = 0.f;
#pragma unroll
        for (int w = 0; w < 8; w++) {
            R += part[(0 * 8 + w) * 32 + lane];
            S += part[(1 * 8 + w) * 32 + lane];
            T += part[(2 * 8 + w) * 32 + lane];
        }
        g_R[nb + lane] = R;
        g_S[nb + lane] = S;
        g_T[nb + lane] = T;

        // per-block err contributions for iterations 1..TMAX (lane = row)
        float u = 1.f;
#pragma unroll
        for (int t = 0; t < TMAX; t++) {
            float denom = (t == 0) ? R : (S / (u + 1e-8f));
            float un = 1.f / (denom + 1e-8f);
            float e = fabsf(un - u);
            u = un;
#pragma unroll
            for (int off = 16; off > 0; off >>= 1)
                e += __shfl_down_sync(0xffffffffu, e, off);
            if (lane == 0) g_Epart[blockIdx.x][t] = e;
        }
    }
}

// ---------------------------------------------------------------------------
// Kernel 2: reduce err partials (redundantly per block), find global stop
// time t*, replay the scalar recurrence t* steps per row, write output.
//   out[n] = u * T[n] / (u + 1e-8)
// ---------------------------------------------------------------------------
__global__ __launch_bounds__(512) void finish_kernel(float* __restrict__ out)
{
    __shared__ float Esum[TMAX];
    const int tid = threadIdx.x;

    if (tid < TMAX) Esum[tid] = 0.f;
    __syncthreads();
    {
        int t = tid & (TMAX - 1);
        int g = tid >> 4;                       // 0..31
        float e = 0.f;
#pragma unroll
        for (int k = 0; k < 4; k++) e += g_Epart[g + 32 * k][t];
        atomicAdd(&Esum[t], e);                 // only integer t* depends on this
    }
    __syncthreads();

    int tstar = 100;                            // fallback: full iteration count
#pragma unroll
    for (int t = TMAX - 1; t >= 0; t--)
        if (Esum[t] < 0.1f * (float)NN) tstar = t + 1;  // first t with mean err < THRESH

    const int n = blockIdx.x * 512 + tid;
    float R = g_R[n], S = g_S[n], T = g_T[n];
    float u = 1.f;
    for (int t = 0; t < tstar; t++) {
        float denom = (t == 0) ? R : (S / (u + 1e-8f));
        u = 1.f / (denom + 1e-8f);
    }
    out[n] = u * T / (u + 1e-8f);
}

extern "C" void kernel_launch(void* const* d_in, const int* in_sizes, int n_in,
                              void* d_out, int out_size)
{
    const float* x = (const float*)d_in[0];  // [4096, 32]
    const float* y = (const float*)d_in[1];  // [512, 32]
    const float* r = (const float*)d_in[2];  // [4096, 512]
    float* out = (float*)d_out;              // [4096]

    cudaFuncSetAttribute(rowstats_kernel,
                         cudaFuncAttributeMaxDynamicSharedMemorySize, SMEM_BYTES);
    rowstats_kernel<<<NBLK, 256, SMEM_BYTES>>>(x, y, r);
    finish_kernel<<<NN / 512, 512>>>(out);
}

// round 6
// speedup vs baseline: 1.1067x; 1.1067x over previous
#include <cuda_runtime.h>
#include <cuda_bf16.h>

#define NN 4096
#define MM 512
#define DD 32
#define NBLK 128        // 32 rows per block
#define NT   512        // 16 warps; each warp owns 32 m-columns x 32 rows

typedef unsigned long long ull;

// sm_103a packed fp32 FMA (FFMA2). Element 0 = low 32 bits.
__device__ __forceinline__ ull ffma2(ull a, ull b, ull c) {
    ull d;
    asm("fma.rn.f32x2 %0, %1, %2, %3;" : "=l"(d) : "l"(a), "l"(b), "l"(c));
    return d;
}
__device__ __forceinline__ ull fdup(float v) {
    unsigned u = __float_as_uint(v);
    return ((ull)u << 32) | (ull)u;
}
__device__ __forceinline__ float flo(ull v) { return __uint_as_float((unsigned)v); }
__device__ __forceinline__ float fhi(ull v) { return __uint_as_float((unsigned)(v >> 32)); }

// Dynamic smem: yT[32][512] | yn2[512] | part[3][16][32]
#define SMEM_FLOATS (32 * 512 + 512 + 3 * 16 * 32)
#define SMEM_BYTES  (SMEM_FLOATS * 4)

// ---------------------------------------------------------------------------
// Single fused kernel. Per block: 32 rows of the Sinkhorn distance.
//   1) stage y transposed in smem (+|y|^2), one m-row per thread
//   2) GEMM-style row stats via packed f32x2 FMAs, lanes = n (broadcast LDS)
//      d2 = |x|^2 + |y|^2 - 2 x.y ;  C = sqrt(d2) ; K = exp(-C/2)
//      R = sum K, S = sum K*r, T = sum K*C*r
//   3) warp 0 combines the 16 warp partials (fixed order), runs the scalar
//      u-recurrence with BLOCK-LOCAL early stop (mean err over 32 rows),
//      writes out[n] = u*T/(u+1e-8).
// ---------------------------------------------------------------------------
__global__ __launch_bounds__(NT) void sinkhorn_fused_kernel(
    const float* __restrict__ x,   // [NN, DD]
    const float* __restrict__ y,   // [MM, DD]
    const float* __restrict__ r,   // [NN, MM]
    float* __restrict__ out)       // [NN]
{
    extern __shared__ float smem_dyn[];
    float* yT   = smem_dyn;              // [d][m] : 32 x 512
    float* yn2  = smem_dyn + 32 * 512;   // [512]
    float* part = yn2 + 512;             // [3][16][32]

    const int tid  = threadIdx.x;
    const int warp = tid >> 5;
    const int lane = tid & 31;
    const int nb   = blockIdx.x << 5;
    const int n    = nb + lane;          // this lane's row (same in every warp)

    // ---- stage y transposed + |y|^2 : thread tid owns m = tid (512 rows).
    //      STS bank = m%32 = lane -> conflict-free.
    {
        const float4* yv = (const float4*)(y + tid * DD);
        float s = 0.f;
#pragma unroll
        for (int k = 0; k < 8; k++) {
            float4 a = yv[k];
            yT[(4 * k + 0) * 512 + tid] = a.x;
            yT[(4 * k + 1) * 512 + tid] = a.y;
            yT[(4 * k + 2) * 512 + tid] = a.z;
            yT[(4 * k + 3) * 512 + tid] = a.w;
            s = fmaf(a.x, a.x, s); s = fmaf(a.y, a.y, s);
            s = fmaf(a.z, a.z, s); s = fmaf(a.w, a.w, s);
        }
        yn2[tid] = s;
    }

    // ---- this lane's x row, duplicated-packed into 32 f32x2 regs + |x|^2
    ull   xd[DD];
    float xn2 = 0.f;
    {
        const float4* xv = (const float4*)(x + n * DD);
#pragma unroll
        for (int k = 0; k < 8; k++) {
            float4 a = xv[k];
            xd[4 * k + 0] = fdup(a.x); xd[4 * k + 1] = fdup(a.y);
            xd[4 * k + 2] = fdup(a.z); xd[4 * k + 3] = fdup(a.w);
            xn2 = fmaf(a.x, a.x, xn2); xn2 = fmaf(a.y, a.y, xn2);
            xn2 = fmaf(a.z, a.z, xn2); xn2 = fmaf(a.w, a.w, xn2);
        }
    }
    __syncthreads();

    // ---- main: this warp's 32-column chunk, 4 m-tiles of 8
    float Racc = 0.f, Sacc = 0.f, Tacc = 0.f;
    const int    mc   = warp << 5;
    const float* rrow = r + (size_t)n * MM;

#pragma unroll
    for (int mt = 0; mt < 4; mt++) {
        const int mb = mc + (mt << 3);
        ull A0 = 0, A1 = 0, A2 = 0, A3 = 0;       // 8 packed dot accumulators
#pragma unroll
        for (int d = 0; d < DD; d++) {
            const ulonglong2* yp = (const ulonglong2*)(yT + d * 512 + mb);
            ulonglong2 p = yp[0];                 // broadcast LDS.128
            ulonglong2 q = yp[1];                 // broadcast LDS.128
            A0 = ffma2(xd[d], p.x, A0);
            A1 = ffma2(xd[d], p.y, A1);
            A2 = ffma2(xd[d], q.x, A2);
            A3 = ffma2(xd[d], q.y, A3);
        }
        float dot[8] = { flo(A0), fhi(A0), flo(A1), fhi(A1),
                         flo(A2), fhi(A2), flo(A3), fhi(A3) };
        float4 r4a = ((const float4*)(rrow + mb))[0];
        float4 r4b = ((const float4*)(rrow + mb))[1];
        float rv[8] = { r4a.x, r4a.y, r4a.z, r4a.w, r4b.x, r4b.y, r4b.z, r4b.w };
        float4 y2a = ((const float4*)(yn2 + mb))[0];
        float4 y2b = ((const float4*)(yn2 + mb))[1];
        float yy[8] = { y2a.x, y2a.y, y2a.z, y2a.w, y2b.x, y2b.y, y2b.z, y2b.w };
#pragma unroll
        for (int j = 0; j < 8; j++) {
            float d2 = fmaf(-2.f, dot[j], xn2 + yy[j]);
            d2 = fmaxf(d2, 0.f);
            float C = sqrtf(d2);
            float K = __expf(-0.5f * C);          // exp(-C/EPS), EPS=2
            Racc += K;
            float Kr = K * rv[j];
            Sacc += Kr;
            Tacc = fmaf(Kr, C, Tacc);
        }
    }

    // ---- combine 16 warp partials in fixed order (deterministic)
    part[(0 * 16 + warp) * 32 + lane] = Racc;
    part[(1 * 16 + warp) * 32 + lane] = Sacc;
    part[(2 * 16 + warp) * 32 + lane] = Tacc;
    __syncthreads();

    if (warp == 0) {
        float R = 0.f, S = 0.f, T = 0.f;
#pragma unroll
        for (int w = 0; w < 16; w++) {
            R += part[(0 * 16 + w) * 32 + lane];
            S += part[(1 * 16 + w) * 32 + lane];
            T += part[(2 * 16 + w) * 32 + lane];
        }

        // Scalar Sinkhorn recurrence with block-local early stop:
        //   iter 1:   u = 1/(R + 1e-8)
        //   iter t>1: u = 1/(S/(u+1e-8) + 1e-8)
        //   stop once mean_32 |u_new - u| < 0.1 (after applying update)
        float u = 1.f;
        bool done = false;
        for (int t = 0; t < 100 && !done; t++) {
            float denom = (t == 0) ? R : (S / (u + 1e-8f));
            float un = 1.f / (denom + 1e-8f);
            float e = fabsf(un - u);
            u = un;
#pragma unroll
            for (int off = 16; off > 0; off >>= 1)
                e += __shfl_xor_sync(0xffffffffu, e, off);
            done = (e < 0.1f * 32.f);             // uniform across warp
        }
        out[n] = u * T / (u + 1e-8f);
    }
}

extern "C" void kernel_launch(void* const* d_in, const int* in_sizes, int n_in,
                              void* d_out, int out_size)
{
    const float* x = (const float*)d_in[0];  // [4096, 32]
    const float* y = (const float*)d_in[1];  // [512, 32]
    const float* r = (const float*)d_in[2];  // [4096, 512]
    float* out = (float*)d_out;              // [4096]

    cudaFuncSetAttribute(sinkhorn_fused_kernel,
                         cudaFuncAttributeMaxDynamicSharedMemorySize, SMEM_BYTES);
    sinkhorn_fused_kernel<<<NBLK, NT, SMEM_BYTES>>>(x, y, r, out);
}

// round 7
// speedup vs baseline: 1.6642x; 1.5038x over previous
#include <cuda_runtime.h>
#include <cuda_bf16.h>

#define NN 4096
#define MM 512
#define DD 32
#define NBLK 128        // 32 rows per block
#define NT   1024       // 32 warps; each warp owns 16 m-columns x 32 rows

typedef unsigned long long ull;

// sm_103a packed fp32 FMA (FFMA2). Element 0 = low 32 bits.
__device__ __forceinline__ ull ffma2(ull a, ull b, ull c) {
    ull d;
    asm("fma.rn.f32x2 %0, %1, %2, %3;" : "=l"(d) : "l"(a), "l"(b), "l"(c));
    return d;
}
__device__ __forceinline__ float flo(ull v) { return __uint_as_float((unsigned)v); }
__device__ __forceinline__ float fhi(ull v) { return __uint_as_float((unsigned)(v >> 32)); }
__device__ __forceinline__ float sqrt_approx(float v) {
    float r;
    asm("sqrt.approx.f32 %0, %1;" : "=f"(r) : "f"(v));
    return r;
}

// ---- smem layout (floats) --------------------------------------------------
#define YS_OFF   0                       // y   [512][32] linear       16384
#define RS_OFF   (YS_OFF + 16384)        // r   [32][516] padded       16512
#define YN2_OFF  (RS_OFF + 16512)        // |y|^2 [512]                  512
#define PP_OFF   (YN2_OFF + 512)         // y sq partials [512][9]      4608
#define PART_OFF (PP_OFF + 4608)         // warp partials [3][32][32]   3072
#define XS_OFF   (PART_OFF + 3072)       // x   [32][36] padded         1152
#define PPX_OFF  (XS_OFF + 1152)         // x sq partials [32][9]        288
#define XN2_OFF  (PPX_OFF + 288)         // |x|^2 [32]                    32
#define SMEM_FLOATS (XN2_OFF + 32)
#define SMEM_BYTES  (SMEM_FLOATS * 4)

// ---------------------------------------------------------------------------
// Single fused kernel, 32 Sinkhorn rows per block.
//  Stage x/y/r coalesced into smem; d-packed f32x2 dot products (both operands
//  are raw float4 reinterprets); C = sqrt(|x|^2+|y|^2-2x.y); K = exp(-C/2);
//  warp partials -> warp 0 runs the scalar u-recurrence with block-local
//  early stop; out[n] = u*T/(u+1e-8).
// ---------------------------------------------------------------------------
__global__ __launch_bounds__(NT) void sinkhorn_fused_kernel(
    const float* __restrict__ x,   // [NN, DD]
    const float* __restrict__ y,   // [MM, DD]
    const float* __restrict__ r,   // [NN, MM]
    float* __restrict__ out)       // [NN]
{
    extern __shared__ float sm[];
    float4*       ys4 = (float4*)(sm + YS_OFF);
    float4*       rs4 = (float4*)(sm + RS_OFF);
    float4*       xs4 = (float4*)(sm + XS_OFF);
    float*        yn2 = sm + YN2_OFF;
    float*        pp  = sm + PP_OFF;
    float*        ppx = sm + PPX_OFF;
    float*        xn2s= sm + XN2_OFF;
    float*        part= sm + PART_OFF;

    const int tid  = threadIdx.x;
    const int warp = tid >> 5;
    const int lane = tid & 31;
    const int nb   = blockIdx.x << 5;

    // ---- coalesced staging -------------------------------------------------
    const float4* yg4 = (const float4*)y;   // 4096 float4
    const float4* rg4 = (const float4*)r;
    const float4* xg4 = (const float4*)x;

#pragma unroll
    for (int k = 0; k < 4; k++) {           // y: linear copy + sq partials
        int idx = tid + 1024 * k;
        float4 a = yg4[idx];
        ys4[idx] = a;
        pp[(idx >> 3) * 9 + (idx & 7)] =
            fmaf(a.x, a.x, fmaf(a.y, a.y, fmaf(a.z, a.z, a.w * a.w)));
    }
#pragma unroll
    for (int k = 0; k < 4; k++) {           // r: [32][516]-padded copy
        int idx = tid + 1024 * k;
        int row = idx >> 7, c4 = idx & 127;
        rs4[row * 129 + c4] = rg4[(size_t)(nb + row) * 128 + c4];
    }
    if (tid < 256) {                        // x: [32][36]-padded copy + sq
        int m = tid >> 3, slot = tid & 7;
        float4 a = xg4[(nb + m) * 8 + slot];
        xs4[m * 9 + slot] = a;
        ppx[m * 9 + slot] =
            fmaf(a.x, a.x, fmaf(a.y, a.y, fmaf(a.z, a.z, a.w * a.w)));
    }
    __syncthreads();

    if (tid < 512) {                        // |y|^2
        float s = 0.f;
#pragma unroll
        for (int j = 0; j < 8; j++) s += pp[tid * 9 + j];
        yn2[tid] = s;
    }
    if (tid < 32) {                         // |x|^2
        float s = 0.f;
#pragma unroll
        for (int j = 0; j < 8; j++) s += ppx[tid * 9 + j];
        xn2s[tid] = s;
    }
    __syncthreads();

    // ---- main: warp owns m-chunk [mc, mc+16); lane owns row n = nb+lane ----
    const int  mc  = warp << 4;
    const float xn2 = xn2s[lane];
    float Racc = 0.f, Sacc = 0.f, Tacc = 0.f;

    const ulonglong2* ys2 = (const ulonglong2*)ys4;
    const ulonglong2* xs2 = (const ulonglong2*)xs4;

#pragma unroll
    for (int mt = 0; mt < 2; mt++) {
        const int mb = mc + (mt << 3);      // m-tile of 8
        ull A[8] = {0, 0, 0, 0, 0, 0, 0, 0};
#pragma unroll
        for (int p2 = 0; p2 < 8; p2++) {    // 4 d's per step (2 packed pairs)
            ulonglong2 xp = xs2[lane * 9 + p2];       // x[n][4p2..4p2+3]
#pragma unroll
            for (int j = 0; j < 8; j++) {
                ulonglong2 yp = ys2[(mb + j) * 8 + p2];  // broadcast LDS.128
                A[j] = ffma2(xp.x, yp.x, A[j]);
                A[j] = ffma2(xp.y, yp.y, A[j]);
            }
        }
        // r for this tile: 2 coalesced-staged float4 (lane-row, 4-way max)
        float4 r4a = rs4[lane * 129 + (mc >> 2) + 2 * mt];
        float4 r4b = rs4[lane * 129 + (mc >> 2) + 2 * mt + 1];
        float rv[8] = { r4a.x, r4a.y, r4a.z, r4a.w, r4b.x, r4b.y, r4b.z, r4b.w };
#pragma unroll
        for (int j = 0; j < 8; j++) {
            float dot = flo(A[j]) + fhi(A[j]);
            float d2  = fmaf(-2.f, dot, xn2 + yn2[mb + j]);
            float C   = sqrt_approx(fmaxf(d2, 0.f));
            float K   = __expf(-0.5f * C);  // exp(-C/EPS), EPS=2
            Racc += K;
            float Kr = K * rv[j];
            Sacc += Kr;
            Tacc = fmaf(Kr, C, Tacc);
        }
    }

    // ---- combine 32 warp partials in fixed order (deterministic) -----------
    part[(0 * 32 + warp) * 32 + lane] = Racc;
    part[(1 * 32 + warp) * 32 + lane] = Sacc;
    part[(2 * 32 + warp) * 32 + lane] = Tacc;
    __syncthreads();

    if (warp == 0) {
        float R = 0.f, S = 0.f, T = 0.f;
#pragma unroll
        for (int w = 0; w < 32; w++) {
            R += part[(0 * 32 + w) * 32 + lane];
            S += part[(1 * 32 + w) * 32 + lane];
            T += part[(2 * 32 + w) * 32 + lane];
        }

        // Scalar Sinkhorn recurrence, block-local early stop:
        //   iter 1:   u = 1/(R + 1e-8)
        //   iter t>1: u = 1/(S/(u+1e-8) + 1e-8)
        //   stop once mean_32 |u_new - u| < 0.1 (after applying update)
        float u = 1.f;
        bool done = false;
        for (int t = 0; t < 100 && !done; t++) {
            float denom = (t == 0) ? R : (S / (u + 1e-8f));
            float un = 1.f / (denom + 1e-8f);
            float e = fabsf(un - u);
            u = un;
#pragma unroll
            for (int off = 16; off > 0; off >>= 1)
                e += __shfl_xor_sync(0xffffffffu, e, off);
            done = (e < 0.1f * 32.f);       // uniform across warp
        }
        out[nb + lane] = u * T / (u + 1e-8f);
    }
}

extern "C" void kernel_launch(void* const* d_in, const int* in_sizes, int n_in,
                              void* d_out, int out_size)
{
    const float* x = (const float*)d_in[0];  // [4096, 32]
    const float* y = (const float*)d_in[1];  // [512, 32]
    const float* r = (const float*)d_in[2];  // [4096, 512]
    float* out = (float*)d_out;              // [4096]

    cudaFuncSetAttribute(sinkhorn_fused_kernel,
                         cudaFuncAttributeMaxDynamicSharedMemorySize, SMEM_BYTES);
    sinkhorn_fused_kernel<<<NBLK, NT, SMEM_BYTES>>>(x, y, r, out);
}